// round 3
// baseline (speedup 1.0000x reference)
#include <cuda_runtime.h>
#include <stdint.h>

// SpinalCPG: T=512 scan over B=2048 batches of 96 LIF neurons + bout/glide FSM.
// One warp per batch; 3 neurons/lane (permuted layout). Per-neuron syn kept in
// registers; segment means computed via shared memory with SEQUENTIAL
// left-to-right sums in original neuron order and true division, using
// non-contracted (__f*_rn) arithmetic to bit-match the XLA reference.
// Warp-uniform glide branch skips noise loads (dominant HBM traffic).

#define T_STEPS 512
#define B_SIZE  2048
#define WARPS_PER_BLOCK 4

__global__ __launch_bounds__(32 * WARPS_PER_BLOCK, 8)
void spinal_cpg_kernel(const float* __restrict__ v0,
                       const float* __restrict__ syn0,
                       const float* __restrict__ noise,
                       const float* __restrict__ drive,
                       const float* __restrict__ turn,
                       const int*   __restrict__ glide0,
                       const int*   __restrict__ bout0,
                       const unsigned char* __restrict__ inbout0,
                       float* __restrict__ out)
{
    __shared__ float syn_sh[WARPS_PER_BLOCK][96];
    __shared__ float means_sh[WARPS_PER_BLOCK][12];   // 10 used, padded

    const int warpInBlk = threadIdx.x >> 5;
    const int warpId = blockIdx.x * WARPS_PER_BLOCK + warpInBlk;
    if (warpId >= B_SIZE) return;
    const int b    = warpId;
    const int lane = threadIdx.x & 31;

    float* ssh = syn_sh[warpInBlk];
    float* msh = means_sh[warpInBlk];

    // ---- permuted neuron -> original-index map (segment-aligned slots) ----
    // slot0: lanes 0-15 -> Lv2a (0..15), 16-31 -> Rv2a (48..63)
    // slot1: 0-11 -> Lmn (28..39), 12-23 -> Rmn (76..87),
    //        24-27 -> Ldi6 (24..27), 28-31 -> Rdi6 (72..75)
    // slot2: 0-7 -> Lv0d (16..23), 8-15 -> Rv0d (64..71),
    //        16-23 -> Lrsh (40..47), 24-31 -> Rrsh (88..95)
    const int o0 = (lane < 16) ? lane : 32 + lane;
    const int o1 = (lane < 12) ? 28 + lane
                 : (lane < 24) ? 64 + lane
                 : (lane < 28) ? lane
                                : 44 + lane;
    const int o2 = (lane < 8)  ? 16 + lane
                 : (lane < 16) ? 56 + lane
                 : (lane < 24) ? 24 + lane
                                : 64 + lane;

    // current-selection predicates (lane-constant)
    const bool p0_L  = (lane < 16);
    const bool p1_mn = (lane < 24);          // slot1: mn vs di6
    const bool p2_v0 = (lane < 16);          // slot2: v0d vs rsh

    // mean indices needed per slot (lane-constant).
    // means layout: 0 Lv2a, 1 Lv0d, 2 Ldi6, 3 Lmn, 4 Lrsh,
    //               5 Rv2a, 6 Rv0d, 7 Rdi6, 8 Rmn, 9 Rrsh
    const int a0 = p0_L ? 6 : 1;   // opposite v0d
    const int a1 = p0_L ? 4 : 9;   // own rsh
    const int a2 = p0_L ? 2 : 7;   // own di6
    const int b0 = (lane < 12) ? 0 : (lane < 24) ? 5 : (lane < 28) ? 0 : 5; // own v2a
    const int b1 = (lane < 12) ? 2 : 7;                                     // own di6 (mn only)
    const int c0 = (lane < 8) ? 0 : (lane < 16) ? 5 : (lane < 24) ? 3 : 8;  // v2a or mn

    // reducer-lane segment table
    const int seg_start_tab[10] = {0, 16, 24, 28, 40, 48, 64, 72, 76, 88};
    const int seg_n_tab[10]     = {16, 8, 4, 12, 8, 16, 8, 4, 12, 8};
    const int my_start = (lane < 10) ? seg_start_tab[lane] : 0;
    const int my_n     = (lane < 10) ? seg_n_tab[lane]     : 0;
    const float my_nf  = (float)my_n;

    // ---- per-neuron state ----
    float vr0 = v0[b * 96 + o0];
    float vr1 = v0[b * 96 + o1];
    float vr2 = v0[b * 96 + o2];
    float sy0 = syn0[b * 96 + o0];
    float sy1 = syn0[b * 96 + o1];
    float sy2 = syn0[b * 96 + o2];

    // ---- per-batch scalars (exact reference order, non-contracted) ----
    const float dr = __ldg(drive + b);
    const float tu = __ldg(turn + b);
    const float drive_L = __fadd_rn(dr, __fmul_rn(fmaxf(0.0f, -tu), 0.3f));
    const float drive_R = __fadd_rn(dr, __fmul_rn(fmaxf(0.0f,  tu), 0.3f));
    const float baseL = __fadd_rn(__fmul_rn(drive_L, 2.0f), 0.5f);
    const float baseR = __fadd_rn(__fmul_rn(drive_R, 2.0f), 0.5f);
    const float base  = p0_L ? baseL : baseR;
    const int bout_len  = max(1, (int)__fmul_rn(dr, 3.0f));
    const int glide_len = max(1, (int)__fmul_rn(__fsub_rn(1.0f, dr), 3.0f));

    int  glide   = __ldg(glide0 + b);
    int  bout    = __ldg(bout0 + b);
    bool in_bout = (__ldg(inbout0 + b) != 0);

    // ---- initial segment means from syn0 (sequential order + division) ----
    ssh[o0] = sy0; ssh[o1] = sy1; ssh[o2] = sy2;
    __syncwarp();
    if (lane < 10) {
        float acc = ssh[my_start];
        for (int i = 1; i < my_n; ++i) acc = __fadd_rn(acc, ssh[my_start + i]);
        msh[lane] = __fdiv_rn(acc, my_nf);
    }
    __syncwarp();

    size_t nbase = (size_t)b * 96;
    const size_t nstride = (size_t)B_SIZE * 96;

    for (int t = 0; t < T_STEPS; ++t, nbase += nstride) {
        float4* op = (float4*)(out + ((size_t)t * B_SIZE + b) * 4);

        if (glide > 0) {                 // warp-uniform: skip all dynamics
            if (lane == 0) *op = make_float4(0.f, 0.f, 0.f, 0.f);
            --glide;
            continue;
        }

        // streamed, read-once noise
        const float n0 = __ldcs(noise + nbase + o0);
        const float n1 = __ldcs(noise + nbase + o1);
        const float n2 = __ldcs(noise + nbase + o2);

        // currents from previous-step means (exact reference association)
        const float I0 = __fsub_rn(__fsub_rn(__fsub_rn(base,
                              __fmul_rn(0.9f, msh[a0])),
                              __fmul_rn(0.6f, msh[a1])),
                              __fmul_rn(0.3f, msh[a2]));
        const float I1 = p1_mn
            ? __fsub_rn(__fmul_rn(0.7f, msh[b0]), __fmul_rn(0.2f, msh[b1]))
            : __fmul_rn(0.4f, msh[b0]);
        const float I2 = p2_v0 ? __fmul_rn(0.6f, msh[c0])
                               : __fmul_rn(0.5f, msh[c0]);

        // I_net = I + noise*0.15 ; v' = 0.5*v + 0.5*I_net (non-contracted)
        const float in0 = __fadd_rn(I0, __fmul_rn(n0, 0.15f));
        const float in1 = __fadd_rn(I1, __fmul_rn(n1, 0.15f));
        const float in2 = __fadd_rn(I2, __fmul_rn(n2, 0.15f));
        float vn0 = __fadd_rn(__fmul_rn(0.5f, vr0), __fmul_rn(0.5f, in0));
        float vn1 = __fadd_rn(__fmul_rn(0.5f, vr1), __fmul_rn(0.5f, in1));
        float vn2 = __fadd_rn(__fmul_rn(0.5f, vr2), __fmul_rn(0.5f, in2));
        const bool spk0 = (vn0 >= 0.5f);
        const bool spk1 = (vn1 >= 0.5f);
        const bool spk2 = (vn2 >= 0.5f);
        vr0 = spk0 ? 0.0f : vn0;
        vr1 = spk1 ? 0.0f : vn1;
        vr2 = spk2 ? 0.0f : vn2;

        // per-neuron syn update: syn' = 0.6*syn + spike
        sy0 = __fadd_rn(__fmul_rn(0.6f, sy0), spk0 ? 1.0f : 0.0f);
        sy1 = __fadd_rn(__fmul_rn(0.6f, sy1), spk1 ? 1.0f : 0.0f);
        sy2 = __fadd_rn(__fmul_rn(0.6f, sy2), spk2 ? 1.0f : 0.0f);

        // publish and reduce (sequential order in original neuron indexing)
        ssh[o0] = sy0; ssh[o1] = sy1; ssh[o2] = sy2;
        __syncwarp();
        if (lane < 10) {
            float acc = ssh[my_start];
            for (int i = 1; i < my_n; ++i) acc = __fadd_rn(acc, ssh[my_start + i]);
            msh[lane] = __fdiv_rn(acc, my_nf);
        }
        __syncwarp();

        // FSM on post-update motor means (uniform across lanes)
        const float mL = msh[3];
        const float mR = msh[8];
        const bool start = (!in_bout) && (fmaxf(mL, mR) > 0.15f);
        if (start) { bout = bout_len; in_bout = true; }
        if (in_bout) --bout;
        const bool end = in_bout && (bout <= 0);
        if (end) { in_bout = false; glide = glide_len; }

        if (lane == 0) {
            const float speed = __fmul_rn(__fadd_rn(mL, mR), 0.5f);
            const float trn   = __fmul_rn(__fsub_rn(mR, mL), 2.0f);
            *op = make_float4(mL, mR, speed, trn);
        }
    }
}

extern "C" void kernel_launch(void* const* d_in, const int* in_sizes, int n_in,
                              void* d_out, int out_size)
{
    const float* v0      = (const float*)d_in[0];
    const float* syn0    = (const float*)d_in[1];
    const float* noise   = (const float*)d_in[2];
    const float* drive   = (const float*)d_in[3];
    const float* turn    = (const float*)d_in[4];
    const int*   glide0  = (const int*)d_in[5];
    const int*   bout0   = (const int*)d_in[6];
    const unsigned char* inbout0 = (const unsigned char*)d_in[7];
    float* out = (float*)d_out;

    const int threads = 32 * WARPS_PER_BLOCK;
    const int blocks  = B_SIZE / WARPS_PER_BLOCK;
    spinal_cpg_kernel<<<blocks, threads>>>(v0, syn0, noise, drive, turn,
                                           glide0, bout0, inbout0, out);
}